// round 13
// baseline (speedup 1.0000x reference)
#include <cuda_runtime.h>
#include <math.h>

#define T_STEPS 4
#define ROWS    8192      // B*N = 8*1024
#define DDIM    512
#define FDIM    2048
#define MTOT    (T_STEPS*ROWS)   // 32768

typedef unsigned int u32;
typedef unsigned long long u64;

// Scratch (device globals -- no runtime allocation allowed)
__device__ float g_h[(size_t)MTOT * FDIM];         // 256 MiB: layer-1 preacts
__device__ float g_y[(size_t)MTOT * DDIM];         //  64 MiB: layer-2 preacts
__device__ u32   g_mask[(size_t)MTOT * (FDIM/32)]; //   8 MiB: spike bitmask

// ---- packed f32x2 helpers (sm_100+: fma.rn.f32x2; ptxas never emits it) ----
__device__ __forceinline__ u64 pack2(float lo, float hi) {
    u64 r; asm("mov.b64 %0, {%1, %2};" : "=l"(r) : "f"(lo), "f"(hi)); return r;
}
__device__ __forceinline__ void unpack2(u64 v, float& lo, float& hi) {
    asm("mov.b64 {%0, %1}, %2;" : "=f"(lo), "=f"(hi) : "l"(v));
}
#define FFMA2(d, a, b) \
    asm("fma.rn.f32x2 %0, %1, %2, %0;" : "+l"(d) : "l"(a), "l"(b))

// ---------------------------------------------------------------------------
// GEMM1: 128x128x16 fp32 SGEMM + bias, packed-f32x2 inner loop (R11/R12).
// Dense A. As row stride padded to 132 floats (store-conflict fix).
// ---------------------------------------------------------------------------
__global__ __launch_bounds__(256, 2)
void sgemm_bias_128(const float* __restrict__ A, const float* __restrict__ B,
                    const float* __restrict__ bias, float* __restrict__ C,
                    int M, int N, int K) {
    const int BK = 16;
    const int AP = 132;
    __shared__ float As[16 * 132];
    __shared__ float Bs[16][128];

    const int tid = threadIdx.x;
    const int bm  = blockIdx.y * 128;
    const int bn  = blockIdx.x * 128;
    const int tr  = (tid >> 4) * 8;
    const int tc  = (tid & 15) * 8;

    u64 acc[8][4];
#pragma unroll
    for (int i = 0; i < 8; i++)
#pragma unroll
        for (int j = 0; j < 4; j++) acc[i][j] = 0ull;

    const float* Aptr = A + (size_t)bm * K;
    const float* Bptr = B + bn;

    for (int kt = 0; kt < K; kt += BK) {
#pragma unroll
        for (int i = 0; i < 2; i++) {
            int id = tid + i * 256;
            int r  = id >> 2;
            int c4 = (id & 3) << 2;
            float4 v = *(const float4*)(Aptr + (size_t)r * K + kt + c4);
            As[(c4 + 0) * AP + r] = v.x;
            As[(c4 + 1) * AP + r] = v.y;
            As[(c4 + 2) * AP + r] = v.z;
            As[(c4 + 3) * AP + r] = v.w;
        }
#pragma unroll
        for (int i = 0; i < 2; i++) {
            int id = tid + i * 256;
            int r  = id >> 5;
            int c  = (id & 31) << 2;
            *(float4*)&Bs[r][c] = *(const float4*)(Bptr + (size_t)(kt + r) * N + c);
        }
        __syncthreads();

#pragma unroll
        for (int k = 0; k < BK; k++) {
            float4 av0 = *(const float4*)&As[k * AP + tr];
            float4 av1 = *(const float4*)&As[k * AP + tr + 4];
            u64 a2[8];
            a2[0] = pack2(av0.x, av0.x);
            a2[1] = pack2(av0.y, av0.y);
            a2[2] = pack2(av0.z, av0.z);
            a2[3] = pack2(av0.w, av0.w);
            a2[4] = pack2(av1.x, av1.x);
            a2[5] = pack2(av1.y, av1.y);
            a2[6] = pack2(av1.z, av1.z);
            a2[7] = pack2(av1.w, av1.w);
            const ulonglong2* bp = (const ulonglong2*)&Bs[k][tc];
            ulonglong2 bv0 = bp[0];
            ulonglong2 bv1 = bp[1];
            u64 b2[4] = {bv0.x, bv0.y, bv1.x, bv1.y};

#pragma unroll
            for (int i = 0; i < 8; i++)
#pragma unroll
                for (int j = 0; j < 4; j++)
                    FFMA2(acc[i][j], a2[i], b2[j]);
        }
        __syncthreads();
    }

#pragma unroll
    for (int i = 0; i < 8; i++) {
        float* Crow = C + (size_t)(bm + tr + i) * N + bn + tc;
#pragma unroll
        for (int j = 0; j < 4; j++) {
            float lo, hi;
            unpack2(acc[i][j], lo, hi);
            Crow[2 * j + 0] = lo + bias[bn + tc + 2 * j + 0];
            Crow[2 * j + 1] = hi + bias[bn + tc + 2 * j + 1];
        }
    }
}

// ---------------------------------------------------------------------------
// GEMM2: 64x128x16 masked-A SGEMM + bias. Grid (4, 512) = 2048 CTAs ->
// 6.92 waves @ 296 slots (98.9% wave eff; the 128-row version quantized to
// 4 waves at 86.5%). A reconstructed from spike bitmask as exact 1.0f/0.0f.
// Thread tile 4 rows x 8 cols (16 u64 accs). Per-output k-chain strictly
// sequential with identical even/odd pairing -> bit-identical trajectory.
// Residency pinned at 2 CTAs/SM via 80 KB dynamic smem floor.
// ---------------------------------------------------------------------------
__global__ __launch_bounds__(256, 2)
void sgemm_bias_64m(const u32* __restrict__ Amask, const float* __restrict__ B,
                    const float* __restrict__ bias, float* __restrict__ C,
                    int M, int N, int K) {
    const int BK = 16;
    const int AP = 68;               // padded A row stride (floats)
    extern __shared__ float smem[];
    float* As = smem;                // 16*68 floats
    float* Bs = smem + 16 * 68;      // 16*128 floats

    const int tid = threadIdx.x;
    const int bm  = blockIdx.y * 64;
    const int bn  = blockIdx.x * 128;
    const int tr  = (tid >> 4) * 4;   // 0..60
    const int tc  = (tid & 15) * 8;   // 0..120

    u64 acc[4][4];
#pragma unroll
    for (int i = 0; i < 4; i++)
#pragma unroll
        for (int j = 0; j < 4; j++) acc[i][j] = 0ull;

    const float* Bptr = B + bn;

    for (int kt = 0; kt < K; kt += BK) {
        // Stage A tile 64x16 from bitmask (1 quad per thread)
        {
            int r  = tid >> 2;
            int c4 = (tid & 3) << 2;
            u32 w = Amask[(size_t)(bm + r) * (K / 32) + (kt >> 5)];
            int sh = (kt & 31) + c4;
            As[(c4 + 0) * AP + r] = ((w >> (sh + 0)) & 1u) ? 1.0f : 0.0f;
            As[(c4 + 1) * AP + r] = ((w >> (sh + 1)) & 1u) ? 1.0f : 0.0f;
            As[(c4 + 2) * AP + r] = ((w >> (sh + 2)) & 1u) ? 1.0f : 0.0f;
            As[(c4 + 3) * AP + r] = ((w >> (sh + 3)) & 1u) ? 1.0f : 0.0f;
        }
        // Load B tile 16x128 (512 float4)
#pragma unroll
        for (int i = 0; i < 2; i++) {
            int id = tid + i * 256;
            int r  = id >> 5;
            int c  = (id & 31) << 2;
            *(float4*)&Bs[r * 128 + c] = *(const float4*)(Bptr + (size_t)(kt + r) * N + c);
        }
        __syncthreads();

#pragma unroll
        for (int k = 0; k < BK; k++) {
            float4 av = *(const float4*)&As[k * AP + tr];
            u64 a2[4];
            a2[0] = pack2(av.x, av.x);
            a2[1] = pack2(av.y, av.y);
            a2[2] = pack2(av.z, av.z);
            a2[3] = pack2(av.w, av.w);
            const ulonglong2* bp = (const ulonglong2*)&Bs[k * 128 + tc];
            ulonglong2 bv0 = bp[0];
            ulonglong2 bv1 = bp[1];
            u64 b2[4] = {bv0.x, bv0.y, bv1.x, bv1.y};

#pragma unroll
            for (int i = 0; i < 4; i++)
#pragma unroll
                for (int j = 0; j < 4; j++)
                    FFMA2(acc[i][j], a2[i], b2[j]);
        }
        __syncthreads();
    }

#pragma unroll
    for (int i = 0; i < 4; i++) {
        float* Crow = C + (size_t)(bm + tr + i) * N + bn + tc;
#pragma unroll
        for (int j = 0; j < 4; j++) {
            float lo, hi;
            unpack2(acc[i][j], lo, hi);
            Crow[2 * j + 0] = lo + bias[bn + tc + 2 * j + 0];
            Crow[2 * j + 1] = hi + bias[bn + tc + 2 * j + 1];
        }
    }
}

// ---------------------------------------------------------------------------
// Block-wide sum reduction
// ---------------------------------------------------------------------------
template <int NT>
__device__ __forceinline__ float block_sum(float val, float* sh) {
    const int lane = threadIdx.x & 31;
    const int warp = threadIdx.x >> 5;
#pragma unroll
    for (int o = 16; o > 0; o >>= 1) val += __shfl_down_sync(0xffffffffu, val, o);
    if (lane == 0) sh[warp] = val;
    __syncthreads();
    const int NW = NT / 32;
    if (warp == 0) {
        float v = (lane < NW) ? sh[lane] : 0.0f;
#pragma unroll
        for (int o = 16; o > 0; o >>= 1) v += __shfl_down_sync(0xffffffffu, v, o);
        if (lane == 0) sh[0] = v;
    }
    __syncthreads();
    float r = sh[0];
    __syncthreads();
    return r;
}

// ---------------------------------------------------------------------------
// Fused LayerNorm + LIF scan. MASK_OUT: emit spike bitmask only (layer 1);
// else dense float out (layer 2 -> d_out).
// ---------------------------------------------------------------------------
template <int FD, int NT, bool MASK_OUT>
__global__ void ln_lif_kernel(const float* __restrict__ in,
                              const float* __restrict__ w,
                              const float* __restrict__ bvec,
                              const float* __restrict__ betap,
                              float* __restrict__ out,
                              u32* __restrict__ maskout) {
    const int VPT = FD / NT;
    const int r   = blockIdx.x;
    const int tid = threadIdx.x;
    const int lane = tid & 31, wid = tid >> 5;
    __shared__ float sh[32];

    float v[T_STEPS][VPT];
    float wv[VPT], bv[VPT];
#pragma unroll
    for (int j = 0; j < VPT; j++) {
        wv[j] = w[tid + j * NT];
        bv[j] = bvec[tid + j * NT];
    }
#pragma unroll
    for (int t = 0; t < T_STEPS; t++) {
        const float* rowp = in + ((size_t)t * ROWS + r) * FD;
#pragma unroll
        for (int j = 0; j < VPT; j++) v[t][j] = rowp[tid + j * NT];
    }

#pragma unroll
    for (int t = 0; t < T_STEPS; t++) {
        float s = 0.0f;
#pragma unroll
        for (int j = 0; j < VPT; j++) s += v[t][j];
        s = block_sum<NT>(s, sh);
        const float mu = s * (1.0f / FD);

        float q = 0.0f;
#pragma unroll
        for (int j = 0; j < VPT; j++) {
            float d = v[t][j] - mu;
            q += d * d;
        }
        q = block_sum<NT>(q, sh);
        const float inv = 1.0f / sqrtf(q * (1.0f / FD) + 1e-5f);

#pragma unroll
        for (int j = 0; j < VPT; j++)
            v[t][j] = (v[t][j] - mu) * inv * wv[j] + bv[j];
    }

    const float beta = *betap;
#pragma unroll
    for (int j = 0; j < VPT; j++) {
        float mem = 0.0f;
#pragma unroll
        for (int t = 0; t < T_STEPS; t++) {
            mem = fmaf(beta, mem, v[t][j]);
            float spk = (mem - 1.0f) > 0.0f ? 1.0f : 0.0f;
            mem -= spk;
            v[t][j] = spk;
        }
    }

#pragma unroll
    for (int t = 0; t < T_STEPS; t++) {
        if (MASK_OUT) {
#pragma unroll
            for (int j = 0; j < VPT; j++) {
                u32 bits = __ballot_sync(0xffffffffu, v[t][j] != 0.0f);
                if (lane == 0)
                    maskout[(size_t)(t * ROWS + r) * (FD / 32) + j * (NT / 32) + wid] = bits;
            }
        } else {
            float* rowp = out + ((size_t)t * ROWS + r) * FD;
#pragma unroll
            for (int j = 0; j < VPT; j++) rowp[tid + j * NT] = v[t][j];
        }
    }
}

// ---------------------------------------------------------------------------
extern "C" void kernel_launch(void* const* d_in, const int* in_sizes, int n_in,
                              void* d_out, int out_size) {
    const float* x     = (const float*)d_in[0];
    const float* W1    = (const float*)d_in[1];
    const float* b1    = (const float*)d_in[2];
    const float* ln1w  = (const float*)d_in[3];
    const float* ln1b  = (const float*)d_in[4];
    const float* beta1 = (const float*)d_in[5];
    const float* W2    = (const float*)d_in[6];
    const float* b2    = (const float*)d_in[7];
    const float* ln2w  = (const float*)d_in[8];
    const float* ln2b  = (const float*)d_in[9];
    const float* beta2 = (const float*)d_in[10];
    float* out = (float*)d_out;

    float *h, *y;
    u32* msk;
    cudaGetSymbolAddress((void**)&h, g_h);
    cudaGetSymbolAddress((void**)&y, g_y);
    cudaGetSymbolAddress((void**)&msk, g_mask);

    // GEMM1: [32768,512] x [512,2048] + b1 -> h   (dense A, 128x128 tiles)
    {
        dim3 grid(FDIM / 128, MTOT / 128);
        sgemm_bias_128<<<grid, 256>>>(x, W1, b1, h, MTOT, FDIM, DDIM);
    }
    // LN1 + LIF1 -> 8 MiB spike bitmask
    ln_lif_kernel<FDIM, 256, true><<<ROWS, 256>>>(h, ln1w, ln1b, beta1, nullptr, msk);

    // GEMM2: spikes(mask) x [2048,512] + b2 -> y  (64x128 tiles, 2048 CTAs)
    {
        const int smem2 = 80 * 1024;   // floor to pin 2 CTAs/SM (228KB / 80KB = 2)
        cudaFuncSetAttribute(sgemm_bias_64m,
                             cudaFuncAttributeMaxDynamicSharedMemorySize, smem2);
        dim3 grid(DDIM / 128, MTOT / 64);
        sgemm_bias_64m<<<grid, 256, smem2>>>(msk, W2, b2, y, MTOT, DDIM, FDIM);
    }
    // LN2 + LIF2 -> d_out
    ln_lif_kernel<DDIM, 128, false><<<ROWS, 128>>>(y, ln2w, ln2b, beta2, out, nullptr);
}

// round 14
// speedup vs baseline: 1.3791x; 1.3791x over previous
#include <cuda_runtime.h>
#include <math.h>

#define T_STEPS 4
#define ROWS    8192      // B*N = 8*1024
#define DDIM    512
#define FDIM    2048
#define MTOT    (T_STEPS*ROWS)   // 32768

typedef unsigned int u32;
typedef unsigned long long u64;

// Scratch (device globals -- no runtime allocation allowed)
__device__ float g_h[(size_t)MTOT * FDIM];         // 256 MiB: layer-1 preacts
__device__ float g_y[(size_t)MTOT * DDIM];         //  64 MiB: layer-2 preacts
__device__ u32   g_mask[(size_t)MTOT * (FDIM/32)]; //   8 MiB: spike bitmask

// ---- packed f32x2 helpers (sm_100+: fma.rn.f32x2; ptxas never emits it) ----
__device__ __forceinline__ u64 pack2(float lo, float hi) {
    u64 r; asm("mov.b64 %0, {%1, %2};" : "=l"(r) : "f"(lo), "f"(hi)); return r;
}
__device__ __forceinline__ void unpack2(u64 v, float& lo, float& hi) {
    asm("mov.b64 {%0, %1}, %2;" : "=f"(lo), "=f"(hi) : "l"(v));
}
#define FFMA2(d, a, b) \
    asm("fma.rn.f32x2 %0, %1, %2, %0;" : "+l"(d) : "l"(a), "l"(b))

// ---------------------------------------------------------------------------
// 128x128x16 fp32 SGEMM with fused bias, packed-f32x2 inner loop (R12).
// MASK_A=false: dense A (GEMM1). MASK_A=true: A reconstructed from spike
// bitmask as exact 1.0f/0.0f (GEMM2) -- identical values and trajectory.
// As row stride padded to 132 floats (store-conflict fix).
// Epilogue vectorized: bias hoisted to 2x float4, C written via STG.128
// (same values, same add order -> bit-identical output).
// ---------------------------------------------------------------------------
template <bool MASK_A>
__global__ __launch_bounds__(256, 2)
void sgemm_bias_128(const float* __restrict__ A, const u32* __restrict__ Amask,
                    const float* __restrict__ B,
                    const float* __restrict__ bias, float* __restrict__ C,
                    int M, int N, int K) {
    const int BK = 16;
    const int AP = 132;              // padded A row stride (floats)
    __shared__ float As[16 * 132];   // ~8.25 KiB
    __shared__ float Bs[16][128];    //  8 KiB

    const int tid = threadIdx.x;
    const int bm  = blockIdx.y * 128;
    const int bn  = blockIdx.x * 128;
    const int tr  = (tid >> 4) * 8;   // 0..120
    const int tc  = (tid & 15) * 8;   // 0..120

    u64 acc[8][4];
#pragma unroll
    for (int i = 0; i < 8; i++)
#pragma unroll
        for (int j = 0; j < 4; j++) acc[i][j] = 0ull;

    const float* Aptr = A + (size_t)bm * K;
    const float* Bptr = B + bn;

    for (int kt = 0; kt < K; kt += BK) {
        // Stage A tile 128x16, transposed into As[k*AP + m]
#pragma unroll
        for (int i = 0; i < 2; i++) {
            int id = tid + i * 256;
            int r  = id >> 2;
            int c4 = (id & 3) << 2;
            if (MASK_A) {
                // spikes: 1 bit each, expand to exact 1.0f / 0.0f
                u32 w = Amask[(size_t)(bm + r) * (K / 32) + (kt >> 5)];
                int sh = (kt & 31) + c4;
                As[(c4 + 0) * AP + r] = ((w >> (sh + 0)) & 1u) ? 1.0f : 0.0f;
                As[(c4 + 1) * AP + r] = ((w >> (sh + 1)) & 1u) ? 1.0f : 0.0f;
                As[(c4 + 2) * AP + r] = ((w >> (sh + 2)) & 1u) ? 1.0f : 0.0f;
                As[(c4 + 3) * AP + r] = ((w >> (sh + 3)) & 1u) ? 1.0f : 0.0f;
            } else {
                float4 v = *(const float4*)(Aptr + (size_t)r * K + kt + c4);
                As[(c4 + 0) * AP + r] = v.x;
                As[(c4 + 1) * AP + r] = v.y;
                As[(c4 + 2) * AP + r] = v.z;
                As[(c4 + 3) * AP + r] = v.w;
            }
        }
        // Load B tile 16x128 (512 float4), direct
#pragma unroll
        for (int i = 0; i < 2; i++) {
            int id = tid + i * 256;
            int r  = id >> 5;
            int c  = (id & 31) << 2;
            *(float4*)&Bs[r][c] = *(const float4*)(Bptr + (size_t)(kt + r) * N + c);
        }
        __syncthreads();

#pragma unroll
        for (int k = 0; k < BK; k++) {
            float4 av0 = *(const float4*)&As[k * AP + tr];
            float4 av1 = *(const float4*)&As[k * AP + tr + 4];
            u64 a2[8];
            a2[0] = pack2(av0.x, av0.x);
            a2[1] = pack2(av0.y, av0.y);
            a2[2] = pack2(av0.z, av0.z);
            a2[3] = pack2(av0.w, av0.w);
            a2[4] = pack2(av1.x, av1.x);
            a2[5] = pack2(av1.y, av1.y);
            a2[6] = pack2(av1.z, av1.z);
            a2[7] = pack2(av1.w, av1.w);
            const ulonglong2* bp = (const ulonglong2*)&Bs[k][tc];
            ulonglong2 bv0 = bp[0];
            ulonglong2 bv1 = bp[1];
            u64 b2[4] = {bv0.x, bv0.y, bv1.x, bv1.y};

#pragma unroll
            for (int i = 0; i < 8; i++)
#pragma unroll
                for (int j = 0; j < 4; j++)
                    FFMA2(acc[i][j], a2[i], b2[j]);
        }
        __syncthreads();
    }

    // Vectorized epilogue: hoisted bias, float4 stores (values/order unchanged)
    const float4 bb0 = *(const float4*)(bias + bn + tc);
    const float4 bb1 = *(const float4*)(bias + bn + tc + 4);
#pragma unroll
    for (int i = 0; i < 8; i++) {
        float* Crow = C + (size_t)(bm + tr + i) * N + bn + tc;
        float l0, h0, l1, h1, l2, h2, l3, h3;
        unpack2(acc[i][0], l0, h0);
        unpack2(acc[i][1], l1, h1);
        unpack2(acc[i][2], l2, h2);
        unpack2(acc[i][3], l3, h3);
        float4 o0, o1;
        o0.x = l0 + bb0.x;  o0.y = h0 + bb0.y;
        o0.z = l1 + bb0.z;  o0.w = h1 + bb0.w;
        o1.x = l2 + bb1.x;  o1.y = h2 + bb1.y;
        o1.z = l3 + bb1.z;  o1.w = h3 + bb1.w;
        *(float4*)(Crow)     = o0;
        *(float4*)(Crow + 4) = o1;
    }
}

// ---------------------------------------------------------------------------
// Block-wide sum reduction
// ---------------------------------------------------------------------------
template <int NT>
__device__ __forceinline__ float block_sum(float val, float* sh) {
    const int lane = threadIdx.x & 31;
    const int warp = threadIdx.x >> 5;
#pragma unroll
    for (int o = 16; o > 0; o >>= 1) val += __shfl_down_sync(0xffffffffu, val, o);
    if (lane == 0) sh[warp] = val;
    __syncthreads();
    const int NW = NT / 32;
    if (warp == 0) {
        float v = (lane < NW) ? sh[lane] : 0.0f;
#pragma unroll
        for (int o = 16; o > 0; o >>= 1) v += __shfl_down_sync(0xffffffffu, v, o);
        if (lane == 0) sh[0] = v;
    }
    __syncthreads();
    float r = sh[0];
    __syncthreads();
    return r;
}

// ---------------------------------------------------------------------------
// Fused LayerNorm + LIF scan. MASK_OUT: emit spike bitmask only (layer 1);
// else dense float out (layer 2 -> d_out).
// ---------------------------------------------------------------------------
template <int FD, int NT, bool MASK_OUT>
__global__ void ln_lif_kernel(const float* __restrict__ in,
                              const float* __restrict__ w,
                              const float* __restrict__ bvec,
                              const float* __restrict__ betap,
                              float* __restrict__ out,
                              u32* __restrict__ maskout) {
    const int VPT = FD / NT;
    const int r   = blockIdx.x;
    const int tid = threadIdx.x;
    const int lane = tid & 31, wid = tid >> 5;
    __shared__ float sh[32];

    float v[T_STEPS][VPT];
    float wv[VPT], bv[VPT];
#pragma unroll
    for (int j = 0; j < VPT; j++) {
        wv[j] = w[tid + j * NT];
        bv[j] = bvec[tid + j * NT];
    }
#pragma unroll
    for (int t = 0; t < T_STEPS; t++) {
        const float* rowp = in + ((size_t)t * ROWS + r) * FD;
#pragma unroll
        for (int j = 0; j < VPT; j++) v[t][j] = rowp[tid + j * NT];
    }

#pragma unroll
    for (int t = 0; t < T_STEPS; t++) {
        float s = 0.0f;
#pragma unroll
        for (int j = 0; j < VPT; j++) s += v[t][j];
        s = block_sum<NT>(s, sh);
        const float mu = s * (1.0f / FD);

        float q = 0.0f;
#pragma unroll
        for (int j = 0; j < VPT; j++) {
            float d = v[t][j] - mu;
            q += d * d;
        }
        q = block_sum<NT>(q, sh);
        const float inv = 1.0f / sqrtf(q * (1.0f / FD) + 1e-5f);

#pragma unroll
        for (int j = 0; j < VPT; j++)
            v[t][j] = (v[t][j] - mu) * inv * wv[j] + bv[j];
    }

    const float beta = *betap;
#pragma unroll
    for (int j = 0; j < VPT; j++) {
        float mem = 0.0f;
#pragma unroll
        for (int t = 0; t < T_STEPS; t++) {
            mem = fmaf(beta, mem, v[t][j]);
            float spk = (mem - 1.0f) > 0.0f ? 1.0f : 0.0f;
            mem -= spk;
            v[t][j] = spk;
        }
    }

#pragma unroll
    for (int t = 0; t < T_STEPS; t++) {
        if (MASK_OUT) {
#pragma unroll
            for (int j = 0; j < VPT; j++) {
                u32 bits = __ballot_sync(0xffffffffu, v[t][j] != 0.0f);
                if (lane == 0)
                    maskout[(size_t)(t * ROWS + r) * (FD / 32) + j * (NT / 32) + wid] = bits;
            }
        } else {
            float* rowp = out + ((size_t)t * ROWS + r) * FD;
#pragma unroll
            for (int j = 0; j < VPT; j++) rowp[tid + j * NT] = v[t][j];
        }
    }
}

// ---------------------------------------------------------------------------
extern "C" void kernel_launch(void* const* d_in, const int* in_sizes, int n_in,
                              void* d_out, int out_size) {
    const float* x     = (const float*)d_in[0];
    const float* W1    = (const float*)d_in[1];
    const float* b1    = (const float*)d_in[2];
    const float* ln1w  = (const float*)d_in[3];
    const float* ln1b  = (const float*)d_in[4];
    const float* beta1 = (const float*)d_in[5];
    const float* W2    = (const float*)d_in[6];
    const float* b2    = (const float*)d_in[7];
    const float* ln2w  = (const float*)d_in[8];
    const float* ln2b  = (const float*)d_in[9];
    const float* beta2 = (const float*)d_in[10];
    float* out = (float*)d_out;

    float *h, *y;
    u32* msk;
    cudaGetSymbolAddress((void**)&h, g_h);
    cudaGetSymbolAddress((void**)&y, g_y);
    cudaGetSymbolAddress((void**)&msk, g_mask);

    // GEMM1: [32768,512] x [512,2048] + b1 -> h   (dense A)
    {
        dim3 grid(FDIM / 128, MTOT / 128);
        sgemm_bias_128<false><<<grid, 256>>>(x, nullptr, W1, b1, h, MTOT, FDIM, DDIM);
    }
    // LN1 + LIF1 -> 8 MiB spike bitmask (no dense spike write)
    ln_lif_kernel<FDIM, 256, true><<<ROWS, 256>>>(h, ln1w, ln1b, beta1, nullptr, msk);

    // GEMM2: spikes(mask) x [2048,512] + b2 -> y  (A expanded from bits)
    {
        dim3 grid(DDIM / 128, MTOT / 128);
        sgemm_bias_128<true><<<grid, 256>>>(nullptr, msk, W2, b2, y, MTOT, DDIM, FDIM);
    }
    // LN2 + LIF2 -> d_out
    ln_lif_kernel<DDIM, 128, false><<<ROWS, 128>>>(y, ln2w, ln2b, beta2, out, nullptr);
}

// round 15
// speedup vs baseline: 1.3928x; 1.0100x over previous
#include <cuda_runtime.h>
#include <math.h>

#define T_STEPS 4
#define ROWS    8192      // B*N = 8*1024
#define DDIM    512
#define FDIM    2048
#define MTOT    (T_STEPS*ROWS)   // 32768

typedef unsigned int u32;
typedef unsigned long long u64;

// Scratch (device globals -- no runtime allocation allowed)
__device__ float g_h[(size_t)MTOT * FDIM];         // 256 MiB: layer-1 preacts
__device__ float g_y[(size_t)MTOT * DDIM];         //  64 MiB: layer-2 preacts
__device__ u32   g_mask[(size_t)MTOT * (FDIM/32)]; //   8 MiB: spike bitmask

// ---- packed f32x2 helpers (sm_100+: fma.rn.f32x2; ptxas never emits it) ----
__device__ __forceinline__ u64 pack2(float lo, float hi) {
    u64 r; asm("mov.b64 %0, {%1, %2};" : "=l"(r) : "f"(lo), "f"(hi)); return r;
}
__device__ __forceinline__ void unpack2(u64 v, float& lo, float& hi) {
    asm("mov.b64 {%0, %1}, %2;" : "=f"(lo), "=f"(hi) : "l"(v));
}
#define FFMA2(d, a, b) \
    asm("fma.rn.f32x2 %0, %1, %2, %0;" : "+l"(d) : "l"(a), "l"(b))

// ---------------------------------------------------------------------------
// 128x128x16 fp32 SGEMM with fused bias, packed-f32x2 inner loop.
// MASK_A=false: A from dense floats (GEMM1).
// MASK_A=true : A reconstructed from spike bitmask as exact 1.0f/0.0f
//               (GEMM2) -- identical values, identical FFMA2 trajectory.
// As row stride padded to 132 floats (store-conflict fix).
// ---------------------------------------------------------------------------
template <bool MASK_A>
__global__ __launch_bounds__(256, 2)
void sgemm_bias_128(const float* __restrict__ A, const u32* __restrict__ Amask,
                    const float* __restrict__ B,
                    const float* __restrict__ bias, float* __restrict__ C,
                    int M, int N, int K) {
    const int BK = 16;
    const int AP = 132;              // padded A row stride (floats)
    __shared__ float As[16 * 132];   // ~8.25 KiB
    __shared__ float Bs[16][128];    //  8 KiB

    const int tid = threadIdx.x;
    const int bm  = blockIdx.y * 128;
    const int bn  = blockIdx.x * 128;
    const int tr  = (tid >> 4) * 8;   // 0..120
    const int tc  = (tid & 15) * 8;   // 0..120

    u64 acc[8][4];
#pragma unroll
    for (int i = 0; i < 8; i++)
#pragma unroll
        for (int j = 0; j < 4; j++) acc[i][j] = 0ull;

    const float* Aptr = A + (size_t)bm * K;
    const float* Bptr = B + bn;

    for (int kt = 0; kt < K; kt += BK) {
        // Stage A tile 128x16, transposed into As[k*AP + m]
#pragma unroll
        for (int i = 0; i < 2; i++) {
            int id = tid + i * 256;
            int r  = id >> 2;
            int c4 = (id & 3) << 2;
            if (MASK_A) {
                // spikes: 1 bit each, expand to exact 1.0f / 0.0f
                u32 w = Amask[(size_t)(bm + r) * (K / 32) + (kt >> 5)];
                int sh = (kt & 31) + c4;
                As[(c4 + 0) * AP + r] = ((w >> (sh + 0)) & 1u) ? 1.0f : 0.0f;
                As[(c4 + 1) * AP + r] = ((w >> (sh + 1)) & 1u) ? 1.0f : 0.0f;
                As[(c4 + 2) * AP + r] = ((w >> (sh + 2)) & 1u) ? 1.0f : 0.0f;
                As[(c4 + 3) * AP + r] = ((w >> (sh + 3)) & 1u) ? 1.0f : 0.0f;
            } else {
                float4 v = *(const float4*)(Aptr + (size_t)r * K + kt + c4);
                As[(c4 + 0) * AP + r] = v.x;
                As[(c4 + 1) * AP + r] = v.y;
                As[(c4 + 2) * AP + r] = v.z;
                As[(c4 + 3) * AP + r] = v.w;
            }
        }
        // Load B tile 16x128 (512 float4), direct
#pragma unroll
        for (int i = 0; i < 2; i++) {
            int id = tid + i * 256;
            int r  = id >> 5;
            int c  = (id & 31) << 2;
            *(float4*)&Bs[r][c] = *(const float4*)(Bptr + (size_t)(kt + r) * N + c);
        }
        __syncthreads();

#pragma unroll
        for (int k = 0; k < BK; k++) {
            float4 av0 = *(const float4*)&As[k * AP + tr];
            float4 av1 = *(const float4*)&As[k * AP + tr + 4];
            u64 a2[8];
            a2[0] = pack2(av0.x, av0.x);
            a2[1] = pack2(av0.y, av0.y);
            a2[2] = pack2(av0.z, av0.z);
            a2[3] = pack2(av0.w, av0.w);
            a2[4] = pack2(av1.x, av1.x);
            a2[5] = pack2(av1.y, av1.y);
            a2[6] = pack2(av1.z, av1.z);
            a2[7] = pack2(av1.w, av1.w);
            const ulonglong2* bp = (const ulonglong2*)&Bs[k][tc];
            ulonglong2 bv0 = bp[0];
            ulonglong2 bv1 = bp[1];
            u64 b2[4] = {bv0.x, bv0.y, bv1.x, bv1.y};

#pragma unroll
            for (int i = 0; i < 8; i++)
#pragma unroll
                for (int j = 0; j < 4; j++)
                    FFMA2(acc[i][j], a2[i], b2[j]);
        }
        __syncthreads();
    }

#pragma unroll
    for (int i = 0; i < 8; i++) {
        float* Crow = C + (size_t)(bm + tr + i) * N + bn + tc;
#pragma unroll
        for (int j = 0; j < 4; j++) {
            float lo, hi;
            unpack2(acc[i][j], lo, hi);
            Crow[2 * j + 0] = lo + bias[bn + tc + 2 * j + 0];
            Crow[2 * j + 1] = hi + bias[bn + tc + 2 * j + 1];
        }
    }
}

// ---------------------------------------------------------------------------
// Block-wide sum reduction
// ---------------------------------------------------------------------------
template <int NT>
__device__ __forceinline__ float block_sum(float val, float* sh) {
    const int lane = threadIdx.x & 31;
    const int warp = threadIdx.x >> 5;
#pragma unroll
    for (int o = 16; o > 0; o >>= 1) val += __shfl_down_sync(0xffffffffu, val, o);
    if (lane == 0) sh[warp] = val;
    __syncthreads();
    const int NW = NT / 32;
    if (warp == 0) {
        float v = (lane < NW) ? sh[lane] : 0.0f;
#pragma unroll
        for (int o = 16; o > 0; o >>= 1) v += __shfl_down_sync(0xffffffffu, v, o);
        if (lane == 0) sh[0] = v;
    }
    __syncthreads();
    float r = sh[0];
    __syncthreads();
    return r;
}

// ---------------------------------------------------------------------------
// Fused LayerNorm + LIF scan. MASK_OUT: emit spike bitmask only (layer 1,
// saves the 256 MiB dense-spike write); else dense float out (layer 2).
// Mask layout is linear in feature index: word w covers features
// [w*32, w*32+32) of its row (j*8+wid == f_base/32 for NT=256).
// ---------------------------------------------------------------------------
template <int FD, int NT, bool MASK_OUT>
__global__ void ln_lif_kernel(const float* __restrict__ in,
                              const float* __restrict__ w,
                              const float* __restrict__ bvec,
                              const float* __restrict__ betap,
                              float* __restrict__ out,
                              u32* __restrict__ maskout) {
    const int VPT = FD / NT;
    const int r   = blockIdx.x;
    const int tid = threadIdx.x;
    const int lane = tid & 31, wid = tid >> 5;
    __shared__ float sh[32];

    float v[T_STEPS][VPT];
    float wv[VPT], bv[VPT];
#pragma unroll
    for (int j = 0; j < VPT; j++) {
        wv[j] = w[tid + j * NT];
        bv[j] = bvec[tid + j * NT];
    }
#pragma unroll
    for (int t = 0; t < T_STEPS; t++) {
        const float* rowp = in + ((size_t)t * ROWS + r) * FD;
#pragma unroll
        for (int j = 0; j < VPT; j++) v[t][j] = rowp[tid + j * NT];
    }

#pragma unroll
    for (int t = 0; t < T_STEPS; t++) {
        float s = 0.0f;
#pragma unroll
        for (int j = 0; j < VPT; j++) s += v[t][j];
        s = block_sum<NT>(s, sh);
        const float mu = s * (1.0f / FD);

        float q = 0.0f;
#pragma unroll
        for (int j = 0; j < VPT; j++) {
            float d = v[t][j] - mu;
            q += d * d;
        }
        q = block_sum<NT>(q, sh);
        const float inv = 1.0f / sqrtf(q * (1.0f / FD) + 1e-5f);

#pragma unroll
        for (int j = 0; j < VPT; j++)
            v[t][j] = (v[t][j] - mu) * inv * wv[j] + bv[j];
    }

    const float beta = *betap;
#pragma unroll
    for (int j = 0; j < VPT; j++) {
        float mem = 0.0f;
#pragma unroll
        for (int t = 0; t < T_STEPS; t++) {
            mem = fmaf(beta, mem, v[t][j]);
            float spk = (mem - 1.0f) > 0.0f ? 1.0f : 0.0f;
            mem -= spk;
            v[t][j] = spk;
        }
    }

#pragma unroll
    for (int t = 0; t < T_STEPS; t++) {
        if (MASK_OUT) {
#pragma unroll
            for (int j = 0; j < VPT; j++) {
                u32 bits = __ballot_sync(0xffffffffu, v[t][j] != 0.0f);
                if (lane == 0)
                    maskout[(size_t)(t * ROWS + r) * (FD / 32) + j * (NT / 32) + wid] = bits;
            }
        } else {
            float* rowp = out + ((size_t)t * ROWS + r) * FD;
#pragma unroll
            for (int j = 0; j < VPT; j++) rowp[tid + j * NT] = v[t][j];
        }
    }
}

// ---------------------------------------------------------------------------
extern "C" void kernel_launch(void* const* d_in, const int* in_sizes, int n_in,
                              void* d_out, int out_size) {
    const float* x     = (const float*)d_in[0];
    const float* W1    = (const float*)d_in[1];
    const float* b1    = (const float*)d_in[2];
    const float* ln1w  = (const float*)d_in[3];
    const float* ln1b  = (const float*)d_in[4];
    const float* beta1 = (const float*)d_in[5];
    const float* W2    = (const float*)d_in[6];
    const float* b2    = (const float*)d_in[7];
    const float* ln2w  = (const float*)d_in[8];
    const float* ln2b  = (const float*)d_in[9];
    const float* beta2 = (const float*)d_in[10];
    float* out = (float*)d_out;

    float *h, *y;
    u32* msk;
    cudaGetSymbolAddress((void**)&h, g_h);
    cudaGetSymbolAddress((void**)&y, g_y);
    cudaGetSymbolAddress((void**)&msk, g_mask);

    // GEMM1: [32768,512] x [512,2048] + b1 -> h   (dense A)
    {
        dim3 grid(FDIM / 128, MTOT / 128);
        sgemm_bias_128<false><<<grid, 256>>>(x, nullptr, W1, b1, h, MTOT, FDIM, DDIM);
    }
    // LN1 + LIF1 -> 8 MiB spike bitmask (no dense spike write)
    ln_lif_kernel<FDIM, 256, true><<<ROWS, 256>>>(h, ln1w, ln1b, beta1, nullptr, msk);

    // GEMM2: spikes(mask) x [2048,512] + b2 -> y  (A expanded from bits)
    {
        dim3 grid(DDIM / 128, MTOT / 128);
        sgemm_bias_128<true><<<grid, 256>>>(nullptr, msk, W2, b2, y, MTOT, DDIM, FDIM);
    }
    // LN2 + LIF2 -> d_out
    ln_lif_kernel<DDIM, 128, false><<<ROWS, 128>>>(y, ln2w, ln2b, beta2, out, nullptr);
}

// round 16
// speedup vs baseline: 1.4164x; 1.0169x over previous
#include <cuda_runtime.h>
#include <math.h>

#define T_STEPS 4
#define ROWS    8192      // B*N = 8*1024
#define DDIM    512
#define FDIM    2048
#define MTOT    (T_STEPS*ROWS)   // 32768

typedef unsigned int u32;
typedef unsigned long long u64;

// Scratch (device globals -- no runtime allocation allowed)
__device__ float g_h[(size_t)MTOT * FDIM];         // 256 MiB: layer-1 preacts
__device__ float g_y[(size_t)MTOT * DDIM];         //  64 MiB: layer-2 preacts
__device__ u32   g_mask[(size_t)MTOT * (FDIM/32)]; //   8 MiB: spike bitmask

// ---- packed f32x2 helpers (sm_100+: fma.rn.f32x2; ptxas never emits it) ----
__device__ __forceinline__ u64 pack2(float lo, float hi) {
    u64 r; asm("mov.b64 %0, {%1, %2};" : "=l"(r) : "f"(lo), "f"(hi)); return r;
}
__device__ __forceinline__ void unpack2(u64 v, float& lo, float& hi) {
    asm("mov.b64 {%0, %1}, %2;" : "=f"(lo), "=f"(hi) : "l"(v));
}
#define FFMA2(d, a, b) \
    asm("fma.rn.f32x2 %0, %1, %2, %0;" : "+l"(d) : "l"(a), "l"(b))

// ---------------------------------------------------------------------------
// 128x128x16 fp32 SGEMM with fused bias, packed-f32x2 inner loop.
// MASK_A=false: A from dense floats (GEMM1).
// MASK_A=true : A reconstructed from spike bitmask as exact 1.0f/0.0f.
// A staging: AP=132 pad + XOR swizzle (r ^ (c4<<1)) -> store conflicts
// 2-way -> NONE. Reads apply the same XOR per k (p flips bits 3-4 only, so
// float4 alignment and broadcast pattern are preserved). Values in smem and
// the k-sequential FFMA2 trajectory are unchanged -> bit-identical output.
// ---------------------------------------------------------------------------
template <bool MASK_A>
__global__ __launch_bounds__(256, 2)
void sgemm_bias_128(const float* __restrict__ A, const u32* __restrict__ Amask,
                    const float* __restrict__ B,
                    const float* __restrict__ bias, float* __restrict__ C,
                    int M, int N, int K) {
    const int BK = 16;
    const int AP = 132;              // padded A row stride (floats)
    __shared__ float As[16 * 132];   // ~8.25 KiB
    __shared__ float Bs[16][128];    //  8 KiB

    const int tid = threadIdx.x;
    const int bm  = blockIdx.y * 128;
    const int bn  = blockIdx.x * 128;
    const int tr  = (tid >> 4) * 8;   // 0..120
    const int tc  = (tid & 15) * 8;   // 0..120

    u64 acc[8][4];
#pragma unroll
    for (int i = 0; i < 8; i++)
#pragma unroll
        for (int j = 0; j < 4; j++) acc[i][j] = 0ull;

    const float* Aptr = A + (size_t)bm * K;
    const float* Bptr = B + bn;

    for (int kt = 0; kt < K; kt += BK) {
        // Stage A tile 128x16, transposed into As[k*AP + (m ^ p(k))]
#pragma unroll
        for (int i = 0; i < 2; i++) {
            int id = tid + i * 256;
            int r  = id >> 2;
            int c4 = (id & 3) << 2;
            int rp = r ^ (c4 << 1);   // p(c4) in {0,8,16,24}: conflict-free banks
            if (MASK_A) {
                // spikes: 1 bit each, expand to exact 1.0f / 0.0f
                u32 w = Amask[(size_t)(bm + r) * (K / 32) + (kt >> 5)];
                int sh = (kt & 31) + c4;
                As[(c4 + 0) * AP + rp] = ((w >> (sh + 0)) & 1u) ? 1.0f : 0.0f;
                As[(c4 + 1) * AP + rp] = ((w >> (sh + 1)) & 1u) ? 1.0f : 0.0f;
                As[(c4 + 2) * AP + rp] = ((w >> (sh + 2)) & 1u) ? 1.0f : 0.0f;
                As[(c4 + 3) * AP + rp] = ((w >> (sh + 3)) & 1u) ? 1.0f : 0.0f;
            } else {
                float4 v = *(const float4*)(Aptr + (size_t)r * K + kt + c4);
                As[(c4 + 0) * AP + rp] = v.x;
                As[(c4 + 1) * AP + rp] = v.y;
                As[(c4 + 2) * AP + rp] = v.z;
                As[(c4 + 3) * AP + rp] = v.w;
            }
        }
        // Load B tile 16x128 (512 float4), direct (already conflict-free)
#pragma unroll
        for (int i = 0; i < 2; i++) {
            int id = tid + i * 256;
            int r  = id >> 5;
            int c  = (id & 31) << 2;
            *(float4*)&Bs[r][c] = *(const float4*)(Bptr + (size_t)(kt + r) * N + c);
        }
        __syncthreads();

#pragma unroll
        for (int k = 0; k < BK; k++) {
            const int trp = tr ^ ((k & 12) << 1);   // undo store swizzle
            float4 av0 = *(const float4*)&As[k * AP + trp];
            float4 av1 = *(const float4*)&As[k * AP + trp + 4];
            u64 a2[8];
            a2[0] = pack2(av0.x, av0.x);
            a2[1] = pack2(av0.y, av0.y);
            a2[2] = pack2(av0.z, av0.z);
            a2[3] = pack2(av0.w, av0.w);
            a2[4] = pack2(av1.x, av1.x);
            a2[5] = pack2(av1.y, av1.y);
            a2[6] = pack2(av1.z, av1.z);
            a2[7] = pack2(av1.w, av1.w);
            const ulonglong2* bp = (const ulonglong2*)&Bs[k][tc];
            ulonglong2 bv0 = bp[0];
            ulonglong2 bv1 = bp[1];
            u64 b2[4] = {bv0.x, bv0.y, bv1.x, bv1.y};

#pragma unroll
            for (int i = 0; i < 8; i++)
#pragma unroll
                for (int j = 0; j < 4; j++)
                    FFMA2(acc[i][j], a2[i], b2[j]);
        }
        __syncthreads();
    }

#pragma unroll
    for (int i = 0; i < 8; i++) {
        float* Crow = C + (size_t)(bm + tr + i) * N + bn + tc;
#pragma unroll
        for (int j = 0; j < 4; j++) {
            float lo, hi;
            unpack2(acc[i][j], lo, hi);
            Crow[2 * j + 0] = lo + bias[bn + tc + 2 * j + 0];
            Crow[2 * j + 1] = hi + bias[bn + tc + 2 * j + 1];
        }
    }
}

// ---------------------------------------------------------------------------
// Block-wide sum reduction
// ---------------------------------------------------------------------------
template <int NT>
__device__ __forceinline__ float block_sum(float val, float* sh) {
    const int lane = threadIdx.x & 31;
    const int warp = threadIdx.x >> 5;
#pragma unroll
    for (int o = 16; o > 0; o >>= 1) val += __shfl_down_sync(0xffffffffu, val, o);
    if (lane == 0) sh[warp] = val;
    __syncthreads();
    const int NW = NT / 32;
    if (warp == 0) {
        float v = (lane < NW) ? sh[lane] : 0.0f;
#pragma unroll
        for (int o = 16; o > 0; o >>= 1) v += __shfl_down_sync(0xffffffffu, v, o);
        if (lane == 0) sh[0] = v;
    }
    __syncthreads();
    float r = sh[0];
    __syncthreads();
    return r;
}

// ---------------------------------------------------------------------------
// Fused LayerNorm + LIF scan. MASK_OUT: emit spike bitmask only (layer 1,
// saves the 256 MiB dense-spike write); else dense float out (layer 2).
// ---------------------------------------------------------------------------
template <int FD, int NT, bool MASK_OUT>
__global__ void ln_lif_kernel(const float* __restrict__ in,
                              const float* __restrict__ w,
                              const float* __restrict__ bvec,
                              const float* __restrict__ betap,
                              float* __restrict__ out,
                              u32* __restrict__ maskout) {
    const int VPT = FD / NT;
    const int r   = blockIdx.x;
    const int tid = threadIdx.x;
    const int lane = tid & 31, wid = tid >> 5;
    __shared__ float sh[32];

    float v[T_STEPS][VPT];
    float wv[VPT], bv[VPT];
#pragma unroll
    for (int j = 0; j < VPT; j++) {
        wv[j] = w[tid + j * NT];
        bv[j] = bvec[tid + j * NT];
    }
#pragma unroll
    for (int t = 0; t < T_STEPS; t++) {
        const float* rowp = in + ((size_t)t * ROWS + r) * FD;
#pragma unroll
        for (int j = 0; j < VPT; j++) v[t][j] = rowp[tid + j * NT];
    }

#pragma unroll
    for (int t = 0; t < T_STEPS; t++) {
        float s = 0.0f;
#pragma unroll
        for (int j = 0; j < VPT; j++) s += v[t][j];
        s = block_sum<NT>(s, sh);
        const float mu = s * (1.0f / FD);

        float q = 0.0f;
#pragma unroll
        for (int j = 0; j < VPT; j++) {
            float d = v[t][j] - mu;
            q += d * d;
        }
        q = block_sum<NT>(q, sh);
        const float inv = 1.0f / sqrtf(q * (1.0f / FD) + 1e-5f);

#pragma unroll
        for (int j = 0; j < VPT; j++)
            v[t][j] = (v[t][j] - mu) * inv * wv[j] + bv[j];
    }

    const float beta = *betap;
#pragma unroll
    for (int j = 0; j < VPT; j++) {
        float mem = 0.0f;
#pragma unroll
        for (int t = 0; t < T_STEPS; t++) {
            mem = fmaf(beta, mem, v[t][j]);
            float spk = (mem - 1.0f) > 0.0f ? 1.0f : 0.0f;
            mem -= spk;
            v[t][j] = spk;
        }
    }

#pragma unroll
    for (int t = 0; t < T_STEPS; t++) {
        if (MASK_OUT) {
#pragma unroll
            for (int j = 0; j < VPT; j++) {
                u32 bits = __ballot_sync(0xffffffffu, v[t][j] != 0.0f);
                if (lane == 0)
                    maskout[(size_t)(t * ROWS + r) * (FD / 32) + j * (NT / 32) + wid] = bits;
            }
        } else {
            float* rowp = out + ((size_t)t * ROWS + r) * FD;
#pragma unroll
            for (int j = 0; j < VPT; j++) rowp[tid + j * NT] = v[t][j];
        }
    }
}

// ---------------------------------------------------------------------------
extern "C" void kernel_launch(void* const* d_in, const int* in_sizes, int n_in,
                              void* d_out, int out_size) {
    const float* x     = (const float*)d_in[0];
    const float* W1    = (const float*)d_in[1];
    const float* b1    = (const float*)d_in[2];
    const float* ln1w  = (const float*)d_in[3];
    const float* ln1b  = (const float*)d_in[4];
    const float* beta1 = (const float*)d_in[5];
    const float* W2    = (const float*)d_in[6];
    const float* b2    = (const float*)d_in[7];
    const float* ln2w  = (const float*)d_in[8];
    const float* ln2b  = (const float*)d_in[9];
    const float* beta2 = (const float*)d_in[10];
    float* out = (float*)d_out;

    float *h, *y;
    u32* msk;
    cudaGetSymbolAddress((void**)&h, g_h);
    cudaGetSymbolAddress((void**)&y, g_y);
    cudaGetSymbolAddress((void**)&msk, g_mask);

    // GEMM1: [32768,512] x [512,2048] + b1 -> h   (dense A)
    {
        dim3 grid(FDIM / 128, MTOT / 128);
        sgemm_bias_128<false><<<grid, 256>>>(x, nullptr, W1, b1, h, MTOT, FDIM, DDIM);
    }
    // LN1 + LIF1 -> 8 MiB spike bitmask (no dense spike write)
    ln_lif_kernel<FDIM, 256, true><<<ROWS, 256>>>(h, ln1w, ln1b, beta1, nullptr, msk);

    // GEMM2: spikes(mask) x [2048,512] + b2 -> y  (A expanded from bits)
    {
        dim3 grid(DDIM / 128, MTOT / 128);
        sgemm_bias_128<true><<<grid, 256>>>(nullptr, msk, W2, b2, y, MTOT, DDIM, FDIM);
    }
    // LN2 + LIF2 -> d_out
    ln_lif_kernel<DDIM, 128, false><<<ROWS, 128>>>(y, ln2w, ln2b, beta2, out, nullptr);
}

// round 17
// speedup vs baseline: 1.4190x; 1.0018x over previous
#include <cuda_runtime.h>
#include <math.h>

#define T_STEPS 4
#define ROWS    8192      // B*N = 8*1024
#define DDIM    512
#define FDIM    2048
#define MTOT    (T_STEPS*ROWS)   // 32768

typedef unsigned int u32;
typedef unsigned long long u64;

// Scratch (device globals -- no runtime allocation allowed)
__device__ float g_h[(size_t)MTOT * FDIM];         // 256 MiB: layer-1 preacts
__device__ float g_y[(size_t)MTOT * DDIM];         //  64 MiB: layer-2 preacts
__device__ u32   g_mask[(size_t)MTOT * (FDIM/32)]; //   8 MiB: spike bitmask

// ---- packed f32x2 helpers (sm_100+: fma.rn.f32x2; ptxas never emits it) ----
__device__ __forceinline__ u64 pack2(float lo, float hi) {
    u64 r; asm("mov.b64 %0, {%1, %2};" : "=l"(r) : "f"(lo), "f"(hi)); return r;
}
__device__ __forceinline__ void unpack2(u64 v, float& lo, float& hi) {
    asm("mov.b64 {%0, %1}, %2;" : "=f"(lo), "=f"(hi) : "l"(v));
}
#define FFMA2(d, a, b) \
    asm("fma.rn.f32x2 %0, %1, %2, %0;" : "+l"(d) : "l"(a), "l"(b))

// ---------------------------------------------------------------------------
// 128x128x16 fp32 SGEMM with fused bias, packed-f32x2 inner loop.
// MASK_A=false: A from dense floats (GEMM1).
// MASK_A=true : A reconstructed from spike bitmask as exact 1.0f/0.0f.
// A staging: AP=132 pad + XOR swizzle (r ^ (c4<<1)) -> conflict-free stores;
// reads undo the XOR per k (bits 3-4 only; float4 alignment preserved).
// NEW vs R16: double-buffered smem with register prefetch, ONE sync per
// tile (load-phase latency hidden now that staging is conflict-free).
// Same k-sequential FFMA2 trajectory -> bit-identical output.
// ---------------------------------------------------------------------------
template <bool MASK_A>
__global__ __launch_bounds__(256, 2)
void sgemm_bias_128(const float* __restrict__ A, const u32* __restrict__ Amask,
                    const float* __restrict__ B,
                    const float* __restrict__ bias, float* __restrict__ C,
                    int M, int N, int K) {
    const int AP = 132;                  // padded A row stride (floats)
    __shared__ float As[2][16 * 132];    // 2 x ~8.25 KiB
    __shared__ float Bs[2][16][128];     // 2 x  8 KiB

    const int tid = threadIdx.x;
    const int bm  = blockIdx.y * 128;
    const int bn  = blockIdx.x * 128;
    const int tr  = (tid >> 4) * 8;   // 0..120
    const int tc  = (tid & 15) * 8;   // 0..120

    // fixed per-thread staging coordinates
    const int r0  = tid >> 2;                 // A row, part 0
    const int c40 = (tid & 3) << 2;           // A col-in-tile, part 0
    const int r1  = (tid + 256) >> 2;
    const int c41 = ((tid + 256) & 3) << 2;
    const int rp0 = r0 ^ (c40 << 1);          // swizzled store rows
    const int rp1 = r1 ^ (c41 << 1);
    const int br0 = tid >> 5,          bc0 = (tid & 31) << 2;
    const int br1 = (tid + 256) >> 5,  bc1 = ((tid + 256) & 31) << 2;

    u64 acc[8][4];
#pragma unroll
    for (int i = 0; i < 8; i++)
#pragma unroll
        for (int j = 0; j < 4; j++) acc[i][j] = 0ull;

    const float* Aptr = A + (size_t)bm * K;
    const float* Bptr = B + bn;

    float4 pa0, pa1, pb0, pb1;
    u32 w0 = 0, w1 = 0;

    // ---- prefetch helpers ----
    auto fetch = [&](int kt) {
        if (MASK_A) {
            w0 = Amask[(size_t)(bm + r0) * (K / 32) + (kt >> 5)];
            w1 = Amask[(size_t)(bm + r1) * (K / 32) + (kt >> 5)];
        } else {
            pa0 = *(const float4*)(Aptr + (size_t)r0 * K + kt + c40);
            pa1 = *(const float4*)(Aptr + (size_t)r1 * K + kt + c41);
        }
        pb0 = *(const float4*)(Bptr + (size_t)(kt + br0) * N + bc0);
        pb1 = *(const float4*)(Bptr + (size_t)(kt + br1) * N + bc1);
    };
    auto stage = [&](int buf, int kt) {
        float* Ad = As[buf];
        if (MASK_A) {
            int sh0 = (kt & 31) + c40;
            Ad[(c40 + 0) * AP + rp0] = ((w0 >> (sh0 + 0)) & 1u) ? 1.0f : 0.0f;
            Ad[(c40 + 1) * AP + rp0] = ((w0 >> (sh0 + 1)) & 1u) ? 1.0f : 0.0f;
            Ad[(c40 + 2) * AP + rp0] = ((w0 >> (sh0 + 2)) & 1u) ? 1.0f : 0.0f;
            Ad[(c40 + 3) * AP + rp0] = ((w0 >> (sh0 + 3)) & 1u) ? 1.0f : 0.0f;
            int sh1 = (kt & 31) + c41;
            Ad[(c41 + 0) * AP + rp1] = ((w1 >> (sh1 + 0)) & 1u) ? 1.0f : 0.0f;
            Ad[(c41 + 1) * AP + rp1] = ((w1 >> (sh1 + 1)) & 1u) ? 1.0f : 0.0f;
            Ad[(c41 + 2) * AP + rp1] = ((w1 >> (sh1 + 2)) & 1u) ? 1.0f : 0.0f;
            Ad[(c41 + 3) * AP + rp1] = ((w1 >> (sh1 + 3)) & 1u) ? 1.0f : 0.0f;
        } else {
            Ad[(c40 + 0) * AP + rp0] = pa0.x;
            Ad[(c40 + 1) * AP + rp0] = pa0.y;
            Ad[(c40 + 2) * AP + rp0] = pa0.z;
            Ad[(c40 + 3) * AP + rp0] = pa0.w;
            Ad[(c41 + 0) * AP + rp1] = pa1.x;
            Ad[(c41 + 1) * AP + rp1] = pa1.y;
            Ad[(c41 + 2) * AP + rp1] = pa1.z;
            Ad[(c41 + 3) * AP + rp1] = pa1.w;
        }
        *(float4*)&Bs[buf][br0][bc0] = pb0;
        *(float4*)&Bs[buf][br1][bc1] = pb1;
    };

    const int nt = K >> 4;

    // prologue: tile 0 -> buffer 0
    fetch(0);
    stage(0, 0);
    __syncthreads();

    for (int t = 0; t < nt; t++) {
        const int cur = t & 1;

        if (t + 1 < nt) fetch((t + 1) << 4);

        const float* Ac = As[cur];
#pragma unroll
        for (int k = 0; k < 16; k++) {
            const int trp = tr ^ ((k & 12) << 1);   // undo store swizzle
            float4 av0 = *(const float4*)&Ac[k * AP + trp];
            float4 av1 = *(const float4*)&Ac[k * AP + trp + 4];
            u64 a2[8];
            a2[0] = pack2(av0.x, av0.x);
            a2[1] = pack2(av0.y, av0.y);
            a2[2] = pack2(av0.z, av0.z);
            a2[3] = pack2(av0.w, av0.w);
            a2[4] = pack2(av1.x, av1.x);
            a2[5] = pack2(av1.y, av1.y);
            a2[6] = pack2(av1.z, av1.z);
            a2[7] = pack2(av1.w, av1.w);
            const ulonglong2* bp = (const ulonglong2*)&Bs[cur][k][tc];
            ulonglong2 bv0 = bp[0];
            ulonglong2 bv1 = bp[1];
            u64 b2[4] = {bv0.x, bv0.y, bv1.x, bv1.y};

#pragma unroll
            for (int i = 0; i < 8; i++)
#pragma unroll
                for (int j = 0; j < 4; j++)
                    FFMA2(acc[i][j], a2[i], b2[j]);
        }

        if (t + 1 < nt) {
            stage(cur ^ 1, (t + 1) << 4);
            __syncthreads();   // publishes next buffer; proves cur consumers done
        }
    }

#pragma unroll
    for (int i = 0; i < 8; i++) {
        float* Crow = C + (size_t)(bm + tr + i) * N + bn + tc;
#pragma unroll
        for (int j = 0; j < 4; j++) {
            float lo, hi;
            unpack2(acc[i][j], lo, hi);
            Crow[2 * j + 0] = lo + bias[bn + tc + 2 * j + 0];
            Crow[2 * j + 1] = hi + bias[bn + tc + 2 * j + 1];
        }
    }
}

// ---------------------------------------------------------------------------
// Block-wide sum reduction
// ---------------------------------------------------------------------------
template <int NT>
__device__ __forceinline__ float block_sum(float val, float* sh) {
    const int lane = threadIdx.x & 31;
    const int warp = threadIdx.x >> 5;
#pragma unroll
    for (int o = 16; o > 0; o >>= 1) val += __shfl_down_sync(0xffffffffu, val, o);
    if (lane == 0) sh[warp] = val;
    __syncthreads();
    const int NW = NT / 32;
    if (warp == 0) {
        float v = (lane < NW) ? sh[lane] : 0.0f;
#pragma unroll
        for (int o = 16; o > 0; o >>= 1) v += __shfl_down_sync(0xffffffffu, v, o);
        if (lane == 0) sh[0] = v;
    }
    __syncthreads();
    float r = sh[0];
    __syncthreads();
    return r;
}

// ---------------------------------------------------------------------------
// Fused LayerNorm + LIF scan. MASK_OUT: emit spike bitmask only (layer 1,
// saves the 256 MiB dense-spike write); else dense float out (layer 2).
// ---------------------------------------------------------------------------
template <int FD, int NT, bool MASK_OUT>
__global__ void ln_lif_kernel(const float* __restrict__ in,
                              const float* __restrict__ w,
                              const float* __restrict__ bvec,
                              const float* __restrict__ betap,
                              float* __restrict__ out,
                              u32* __restrict__ maskout) {
    const int VPT = FD / NT;
    const int r   = blockIdx.x;
    const int tid = threadIdx.x;
    const int lane = tid & 31, wid = tid >> 5;
    __shared__ float sh[32];

    float v[T_STEPS][VPT];
    float wv[VPT], bv[VPT];
#pragma unroll
    for (int j = 0; j < VPT; j++) {
        wv[j] = w[tid + j * NT];
        bv[j] = bvec[tid + j * NT];
    }
#pragma unroll
    for (int t = 0; t < T_STEPS; t++) {
        const float* rowp = in + ((size_t)t * ROWS + r) * FD;
#pragma unroll
        for (int j = 0; j < VPT; j++) v[t][j] = rowp[tid + j * NT];
    }

#pragma unroll
    for (int t = 0; t < T_STEPS; t++) {
        float s = 0.0f;
#pragma unroll
        for (int j = 0; j < VPT; j++) s += v[t][j];
        s = block_sum<NT>(s, sh);
        const float mu = s * (1.0f / FD);

        float q = 0.0f;
#pragma unroll
        for (int j = 0; j < VPT; j++) {
            float d = v[t][j] - mu;
            q += d * d;
        }
        q = block_sum<NT>(q, sh);
        const float inv = 1.0f / sqrtf(q * (1.0f / FD) + 1e-5f);

#pragma unroll
        for (int j = 0; j < VPT; j++)
            v[t][j] = (v[t][j] - mu) * inv * wv[j] + bv[j];
    }

    const float beta = *betap;
#pragma unroll
    for (int j = 0; j < VPT; j++) {
        float mem = 0.0f;
#pragma unroll
        for (int t = 0; t < T_STEPS; t++) {
            mem = fmaf(beta, mem, v[t][j]);
            float spk = (mem - 1.0f) > 0.0f ? 1.0f : 0.0f;
            mem -= spk;
            v[t][j] = spk;
        }
    }

#pragma unroll
    for (int t = 0; t < T_STEPS; t++) {
        if (MASK_OUT) {
#pragma unroll
            for (int j = 0; j < VPT; j++) {
                u32 bits = __ballot_sync(0xffffffffu, v[t][j] != 0.0f);
                if (lane == 0)
                    maskout[(size_t)(t * ROWS + r) * (FD / 32) + j * (NT / 32) + wid] = bits;
            }
        } else {
            float* rowp = out + ((size_t)t * ROWS + r) * FD;
#pragma unroll
            for (int j = 0; j < VPT; j++) rowp[tid + j * NT] = v[t][j];
        }
    }
}

// ---------------------------------------------------------------------------
extern "C" void kernel_launch(void* const* d_in, const int* in_sizes, int n_in,
                              void* d_out, int out_size) {
    const float* x     = (const float*)d_in[0];
    const float* W1    = (const float*)d_in[1];
    const float* b1    = (const float*)d_in[2];
    const float* ln1w  = (const float*)d_in[3];
    const float* ln1b  = (const float*)d_in[4];
    const float* beta1 = (const float*)d_in[5];
    const float* W2    = (const float*)d_in[6];
    const float* b2    = (const float*)d_in[7];
    const float* ln2w  = (const float*)d_in[8];
    const float* ln2b  = (const float*)d_in[9];
    const float* beta2 = (const float*)d_in[10];
    float* out = (float*)d_out;

    float *h, *y;
    u32* msk;
    cudaGetSymbolAddress((void**)&h, g_h);
    cudaGetSymbolAddress((void**)&y, g_y);
    cudaGetSymbolAddress((void**)&msk, g_mask);

    // GEMM1: [32768,512] x [512,2048] + b1 -> h   (dense A)
    {
        dim3 grid(FDIM / 128, MTOT / 128);
        sgemm_bias_128<false><<<grid, 256>>>(x, nullptr, W1, b1, h, MTOT, FDIM, DDIM);
    }
    // LN1 + LIF1 -> 8 MiB spike bitmask (no dense spike write)
    ln_lif_kernel<FDIM, 256, true><<<ROWS, 256>>>(h, ln1w, ln1b, beta1, nullptr, msk);

    // GEMM2: spikes(mask) x [2048,512] + b2 -> y  (A expanded from bits)
    {
        dim3 grid(DDIM / 128, MTOT / 128);
        sgemm_bias_128<true><<<grid, 256>>>(nullptr, msk, W2, b2, y, MTOT, DDIM, FDIM);
    }
    // LN2 + LIF2 -> d_out
    ln_lif_kernel<DDIM, 128, false><<<ROWS, 128>>>(y, ln2w, ln2b, beta2, out, nullptr);
}